// round 1
// baseline (speedup 1.0000x reference)
#include <cuda_runtime.h>
#include <math.h>

// MyLoss: masked gather-NLL over [B=16, L=512, V=32000] logits.
// Only ~B*L gathered logits are ever needed -> latency-bound, not BW-bound.

#define PAD_TOK 0
#define UNK_TOK 1
#define END_TOK 2

// Per-batch partial results (scratch; device global per allocation rules).
__device__ float g_sent_loss[64];

__global__ void myloss_per_batch(const float* __restrict__ logits,
                                 const int*   __restrict__ forwarded_trgs,
                                 const int*   __restrict__ targets,
                                 const int*   __restrict__ sequence_lengths,
                                 const int*   __restrict__ inserted,
                                 int L, int V)
{
    const int b   = blockIdx.x;
    const int tid = threadIdx.x;   // == l, blockDim.x == L

    __shared__ int   s_first_pad;
    __shared__ float s_red[512];

    if (tid == 0) s_first_pad = L;
    __syncthreads();

    // Load this position's forwarded target; find first PAD position.
    const int base = b * L;
    const int f = forwarded_trgs[base + tid];
    if (f == PAD_TOK) atomicMin(&s_first_pad, tid);
    __syncthreads();
    const int first_pad = s_first_pad;

    // unk mask: strictly before first PAD and token == UNK
    float loss = 0.0f;
    if (tid < first_pad && f == UNK_TOK) {
        const int prev = (tid == 0) ? (L - 1) : (tid - 1);   // roll(targets, 1)
        const int t    = targets[base + prev];
        const float p  = logits[(long long)(base + tid) * V + t];
        loss = -logf(p);
    }

    // Deterministic tree reduction over L=512 lanes.
    s_red[tid] = loss;
    __syncthreads();
    #pragma unroll
    for (int s = 256; s > 0; s >>= 1) {
        if (tid < s) s_red[tid] += s_red[tid + s];
        __syncthreads();
    }

    if (tid == 0) {
        const float loss_sum = s_red[0];
        const int   sl       = sequence_lengths[b];
        float sent_loss;
        if (loss_sum == 0.0f) {
            // fallback: -log(logits[b, sl+2, END]) / L   (sl+2 < L guaranteed)
            const float pe = logits[(long long)(base + sl + 2) * V + END_TOK];
            sent_loss = -logf(pe) / (float)L;
        } else {
            sent_loss = loss_sum / (float)L;
        }
        g_sent_loss[b] = (inserted[b] < sl) ? sent_loss : 0.0f;
    }
}

// Fixed-order final sum -> deterministic scalar output.
__global__ void myloss_finalize(float* __restrict__ out, int B)
{
    float s = 0.0f;
    for (int i = 0; i < B; ++i) s += g_sent_loss[i];
    out[0] = s;
}

extern "C" void kernel_launch(void* const* d_in, const int* in_sizes, int n_in,
                              void* d_out, int out_size)
{
    const float* logits           = (const float*)d_in[0];
    const int*   forwarded_trgs   = (const int*)  d_in[1];
    const int*   targets          = (const int*)  d_in[2];
    const int*   sequence_lengths = (const int*)  d_in[3];
    const int*   inserted         = (const int*)  d_in[4];

    const int B = in_sizes[3];              // sequence_lengths is [B]
    const int L = in_sizes[1] / B;          // forwarded_trgs is [B, L]
    const int V = (int)((long long)in_sizes[0] / ((long long)B * L));

    myloss_per_batch<<<B, L>>>(logits, forwarded_trgs, targets,
                               sequence_lengths, inserted, L, V);
    myloss_finalize<<<1, 1>>>((float*)d_out, B);
}

// round 2
// speedup vs baseline: 1.0048x; 1.0048x over previous
#include <cuda_runtime.h>
#include <math.h>

// MyLoss fused single-kernel: one block, warp w = batch b.
// [B=16, L=512, V=32000]; only gathered logits are touched -> latency floor.

#define PAD_TOK 0
#define UNK_TOK 1
#define END_TOK 2

__global__ void myloss_fused(const float* __restrict__ logits,
                             const int*   __restrict__ forwarded_trgs,
                             const int*   __restrict__ targets,
                             const int*   __restrict__ sequence_lengths,
                             const int*   __restrict__ inserted,
                             float*       __restrict__ out,
                             int B, int L, int V)
{
    const int w    = threadIdx.x >> 5;   // batch index
    const int lane = threadIdx.x & 31;
    const int b    = w;
    const int base = b * L;
    const int ITER = L / 32;             // 16 for L=512

    __shared__ float s_sent[32];

    // ---- Early independent chain (lane 0): fallback END-logit gather ----
    int   sl = 0, ins = 0;
    float pe = 1.0f;
    if (lane == 0) {
        sl  = sequence_lengths[b];
        ins = inserted[b];
        pe  = logits[(long long)(base + sl + 2) * V + END_TOK];  // dependent chain, starts NOW
    }

    // ---- Front-batched loads: forwarded + shifted targets (all independent) ----
    int f[16], t[16];
    #pragma unroll
    for (int i = 0; i < 16; ++i) {
        const int pos = i * 32 + lane;
        f[i] = forwarded_trgs[base + pos];
    }
    #pragma unroll
    for (int i = 0; i < 16; ++i) {
        const int pos  = i * 32 + lane;
        const int prev = (pos == 0) ? (L - 1) : (pos - 1);       // roll(targets,1)
        t[i] = targets[base + prev];
    }

    // ---- First-PAD position: per-lane min, then warp min-reduce (shuffles) ----
    int fp = L;
    #pragma unroll
    for (int i = 0; i < 16; ++i) {
        const int pos = i * 32 + lane;
        if (f[i] == PAD_TOK && pos < fp) fp = pos;
    }
    #pragma unroll
    for (int s = 16; s > 0; s >>= 1)
        fp = min(fp, __shfl_xor_sync(0xffffffffu, fp, s));

    // ---- Masked logit gathers (addresses already known from t[]) ----
    float loss = 0.0f;
    #pragma unroll
    for (int i = 0; i < 16; ++i) {
        const int pos = i * 32 + lane;
        if (pos < fp && f[i] == UNK_TOK) {
            const float p = logits[(long long)(base + pos) * V + t[i]];
            loss += -logf(p);
        }
    }
    // Deterministic warp sum-reduce.
    #pragma unroll
    for (int s = 16; s > 0; s >>= 1)
        loss += __shfl_xor_sync(0xffffffffu, loss, s);

    if (lane == 0) {
        float sent;
        if (loss == 0.0f) sent = -logf(pe) / (float)L;           // fallback
        else              sent = loss / (float)L;
        s_sent[b] = (ins < sl) ? sent : 0.0f;
    }
    __syncthreads();

    // ---- Fixed-order final sum (deterministic) ----
    if (threadIdx.x == 0) {
        float s = 0.0f;
        for (int i = 0; i < B; ++i) s += s_sent[i];
        out[0] = s;
    }
}

extern "C" void kernel_launch(void* const* d_in, const int* in_sizes, int n_in,
                              void* d_out, int out_size)
{
    const float* logits           = (const float*)d_in[0];
    const int*   forwarded_trgs   = (const int*)  d_in[1];
    const int*   targets          = (const int*)  d_in[2];
    const int*   sequence_lengths = (const int*)  d_in[3];
    const int*   inserted         = (const int*)  d_in[4];

    const int B = in_sizes[3];                                   // [B]
    const int L = in_sizes[1] / B;                               // [B, L]
    const int V = (int)((long long)in_sizes[0] / ((long long)B * L));

    myloss_fused<<<1, B * 32>>>(logits, forwarded_trgs, targets,
                                sequence_lengths, inserted,
                                (float*)d_out, B, L, V);
}